// round 3
// baseline (speedup 1.0000x reference)
#include <cuda_runtime.h>
#include <cstdint>

// ---------------------------------------------------------------------------
// Problem constants (fixed by setup_inputs)
// ---------------------------------------------------------------------------
#define BATCH   2
#define SEQ     2048
#define MROWS   (BATCH*SEQ)      // 4096
#define EMBD    2048
#define NHEAD   16
#define NKV     8
#define HDIM    128
#define HALF    64

// ---------------------------------------------------------------------------
// Device scratch (no cudaMalloc allowed)
// ---------------------------------------------------------------------------
__device__ float d_Qraw[(size_t)MROWS*EMBD];        // 32 MB  x@wq
__device__ float d_Kraw[(size_t)MROWS*NKV*HDIM];    // 16 MB  x@wk
__device__ float d_Vbuf[(size_t)MROWS*NKV*HDIM];    // 16 MB  x@wv, then gated in place
__device__ float d_Qt[(size_t)BATCH*NHEAD*HDIM*SEQ];// 32 MB  q normed, [b][h][d][t]
__device__ float d_Kt[(size_t)BATCH*NKV*HDIM*SEQ];  // 16 MB  k normed, [b][kvh][d][t]
__device__ float d_G[(size_t)MROWS*NKV];            // ve gate
__device__ float d_AG[(size_t)MROWS*NHEAD];         // attn gate
__device__ float d_Y[(size_t)MROWS*EMBD];           // 32 MB  attention output

// ---------------------------------------------------------------------------
// Generic fp32 SGEMM: C[M,N] = A[M,K] @ B[K,N], row-major, optional (1+s) scale
// BM=BN=128, BK=8, 256 threads, 8x8 microtile
// ---------------------------------------------------------------------------
__global__ void __launch_bounds__(256) sgemm_kernel(
    const float* __restrict__ A, const float* __restrict__ B,
    float* __restrict__ C, int M, int N, int K,
    const float* __restrict__ scale_ptr)
{
    __shared__ float As[8*128];   // transposed: As[k][m]
    __shared__ float Bs[8*128];   // Bs[k][n]

    const int tid  = threadIdx.x;
    const int m0   = blockIdx.y * 128;
    const int n0   = blockIdx.x * 128;
    const int tRow = tid >> 4;        // 0..15
    const int tCol = tid & 15;        // 0..15

    const int aRow = tid >> 1;        // 0..127
    const int aCol = (tid & 1) * 4;   // 0 or 4
    const int bRow = tid >> 5;        // 0..7
    const int bCol = (tid & 31) * 4;  // 0..124

    const float* Ag = A + (size_t)(m0 + aRow) * K + aCol;
    const float* Bg = B + (size_t)bRow * N + n0 + bCol;

    float acc[8][8];
#pragma unroll
    for (int i = 0; i < 8; ++i)
#pragma unroll
        for (int j = 0; j < 8; ++j) acc[i][j] = 0.f;

    for (int k0 = 0; k0 < K; k0 += 8) {
        float4 av = *(const float4*)(Ag + k0);
        float4 bv = *(const float4*)(Bg + (size_t)k0 * N);
        __syncthreads();
        As[(aCol + 0)*128 + aRow] = av.x;
        As[(aCol + 1)*128 + aRow] = av.y;
        As[(aCol + 2)*128 + aRow] = av.z;
        As[(aCol + 3)*128 + aRow] = av.w;
        *(float4*)(Bs + bRow*128 + bCol) = bv;
        __syncthreads();
#pragma unroll
        for (int kk = 0; kk < 8; ++kk) {
            float4 a0 = *(float4*)(As + kk*128 + tRow*8);
            float4 a1 = *(float4*)(As + kk*128 + tRow*8 + 4);
            float4 b0 = *(float4*)(Bs + kk*128 + tCol*8);
            float4 b1 = *(float4*)(Bs + kk*128 + tCol*8 + 4);
            float a[8] = {a0.x,a0.y,a0.z,a0.w,a1.x,a1.y,a1.z,a1.w};
            float b[8] = {b0.x,b0.y,b0.z,b0.w,b1.x,b1.y,b1.z,b1.w};
#pragma unroll
            for (int i = 0; i < 8; ++i)
#pragma unroll
                for (int j = 0; j < 8; ++j)
                    acc[i][j] += a[i] * b[j];
        }
    }

    float scl = 1.0f;
    if (scale_ptr) scl = 1.0f + scale_ptr[0];

#pragma unroll
    for (int i = 0; i < 8; ++i) {
        float* Cp = C + (size_t)(m0 + tRow*8 + i) * N + n0 + tCol*8;
        float4 o0 = make_float4(acc[i][0]*scl, acc[i][1]*scl, acc[i][2]*scl, acc[i][3]*scl);
        float4 o1 = make_float4(acc[i][4]*scl, acc[i][5]*scl, acc[i][6]*scl, acc[i][7]*scl);
        *(float4*)(Cp)     = o0;
        *(float4*)(Cp + 4) = o1;
    }
}

// ---------------------------------------------------------------------------
// Gates: G[m][kvh] = 2*sigmoid(x[m,:32] @ w_ve_gate[:,kvh])
//        AG[m][h]  =   sigmoid(x[m,:12] @ w_attn_gate[:,h])
// ---------------------------------------------------------------------------
__global__ void gates_kernel(const float* __restrict__ x,
                             const float* __restrict__ wg,   // [32][8]
                             const float* __restrict__ wa,   // [12][16]
                             float* __restrict__ G, float* __restrict__ AG)
{
    int job = blockIdx.x * blockDim.x + threadIdx.x;
    if (job >= MROWS * 24) return;
    int m = job / 24;
    int s = job - m * 24;
    const float* xr = x + (size_t)m * EMBD;
    if (s < 8) {
        float acc = 0.f;
#pragma unroll
        for (int c = 0; c < 32; ++c) acc += xr[c] * wg[c*8 + s];
        G[m*8 + s] = 2.0f / (1.0f + __expf(-acc));
    } else {
        int h = s - 8;
        float acc = 0.f;
#pragma unroll
        for (int c = 0; c < 12; ++c) acc += xr[c] * wa[c*16 + h];
        AG[m*16 + h] = 1.0f / (1.0f + __expf(-acc));
    }
}

// ---------------------------------------------------------------------------
// Post: k-shift + RoPE + RMSNorm for q,k (written d-major [b][head][d][t]);
//       v += gate * ve (in place).  One warp per (row, slot), slot: 16 q heads,
//       8 k heads, 8 v heads.
// ---------------------------------------------------------------------------
__global__ void post_kernel(const float* __restrict__ Qraw,
                            const float* __restrict__ Kraw,
                            float* __restrict__ Vb,
                            const float* __restrict__ ve,
                            const float* __restrict__ cosp,   // [T][64]
                            const float* __restrict__ sinp,
                            const float* __restrict__ G,
                            float* __restrict__ Qt,
                            float* __restrict__ Kt)
{
    int gw   = (blockIdx.x * blockDim.x + threadIdx.x) >> 5;
    int lane = threadIdx.x & 31;
    int m    = gw >> 5;        // row 0..4095
    int slot = gw & 31;
    int b = m >> 11;           // /SEQ
    int t = m & (SEQ - 1);

    if (slot < 24) {
        float r0, r1, r2, r3;
        float* dst;
        if (slot < 16) {
            int h = slot;
            const float* base = Qraw + (size_t)m * EMBD + h * HDIM;
            r0 = base[lane];      r1 = base[lane + 32];
            r2 = base[lane + 64]; r3 = base[lane + 96];
            dst = Qt + ((size_t)(b*NHEAD + h) * HDIM) * SEQ + t;
        } else {
            int kvh = slot - 16;
            int mprev = (t > 0) ? (m - 1) : m;   // k-shift: upper half from t-1
            const float* bl = Kraw + (size_t)m     * (NKV*HDIM) + kvh * HDIM;
            const float* bu = Kraw + (size_t)mprev * (NKV*HDIM) + kvh * HDIM;
            r0 = bl[lane];      r1 = bl[lane + 32];
            r2 = bu[lane + 64]; r3 = bu[lane + 96];
            dst = Kt + ((size_t)(b*NKV + kvh) * HDIM) * SEQ + t;
        }
        float c0 = cosp[t*HALF + lane], c1 = cosp[t*HALF + lane + 32];
        float s0 = sinp[t*HALF + lane], s1 = sinp[t*HALF + lane + 32];
        // rope: out[:64] = t1*cos + t2*sin ; out[64:] = -t1*sin + t2*cos
        float o0 = r0*c0 + r2*s0;
        float o1 = r1*c1 + r3*s1;
        float o2 = r2*c0 - r0*s0;
        float o3 = r3*c1 - r1*s1;
        float ss = o0*o0 + o1*o1 + o2*o2 + o3*o3;
#pragma unroll
        for (int off = 16; off; off >>= 1)
            ss += __shfl_xor_sync(0xffffffffu, ss, off);
        float rn = rsqrtf(ss * (1.0f/128.0f) + 1.1920929e-7f);
        dst[(size_t)lane        * SEQ] = o0 * rn;
        dst[(size_t)(lane + 32) * SEQ] = o1 * rn;
        dst[(size_t)(lane + 64) * SEQ] = o2 * rn;
        dst[(size_t)(lane + 96) * SEQ] = o3 * rn;
    } else {
        int kvh = slot - 24;
        float g = G[m*8 + kvh];
        size_t off = (size_t)m * (NKV*HDIM) + kvh * HDIM;
#pragma unroll
        for (int d = lane; d < HDIM; d += 32)
            Vb[off + d] = Vb[off + d] + g * ve[off + d];
    }
}

// ---------------------------------------------------------------------------
// Flash attention, fp32, sliding window (0 <= dist <= W).
// Block: (q-block 128, head, batch), 256 threads.
// smem: Qs[128 d][128 q] + Ks[128 d][64 k] + Vs[64 k][128 d] + Ps[64 k][129]
// ---------------------------------------------------------------------------
#define ATTN_SMEM_FLOATS (128*128 + 128*64 + 64*128 + 64*129)
#define ATTN_SMEM_BYTES  (ATTN_SMEM_FLOATS * 4)

__global__ void __launch_bounds__(256, 1) attn_kernel(
    const float* __restrict__ Qt, const float* __restrict__ Kt,
    const float* __restrict__ V,  const float* __restrict__ AG,
    float* __restrict__ Y, const int* __restrict__ wptr)
{
    extern __shared__ float sm[];
    float* Qs = sm;                       // [128][128]
    float* Ks = Qs + 128*128;             // [128][64]
    float* Vs = Ks + 128*64;              // [64][128]
    float* Ps = Vs + 64*128;              // [64][129]

    const int tid = threadIdx.x;
    const int tx = tid & 15;              // key / dim direction
    const int ty = tid >> 4;              // query-row group (8 rows each)
    const int qb = blockIdx.x, h = blockIdx.y, b = blockIdx.z;
    const int kvh = h >> 1;
    const int q0 = qb * 128;

    // window size (robust to int32 / float payload; default 1024)
    int W = 1024;
    if (wptr) {
        int iv = wptr[0];
        if (iv > 0 && iv < (1 << 20)) W = iv;
        else {
            float fv = __int_as_float(iv);
            if (fv > 0.f && fv < 1.0e6f) W = (int)fv;
        }
    }

    // ---- load Q tile (d-major global -> conflict-free smem) ----
    const float* qbase = Qt + ((size_t)(b*NHEAD + h) * HDIM) * SEQ + q0;
#pragma unroll
    for (int r = 0; r < 16; ++r) {
        int id = tid + r*256;             // 0..4095 float4 groups
        int d  = id >> 5;
        int c4 = (id & 31) << 2;
        float4 v = *(const float4*)(qbase + (size_t)d * SEQ + c4);
        *(float4*)(Qs + d*128 + c4) = v;
    }

    float m_r[8], l_r[8], Ov[8][8];
#pragma unroll
    for (int i = 0; i < 8; ++i) {
        m_r[i] = -1.0e30f; l_r[i] = 0.f;
#pragma unroll
        for (int j = 0; j < 8; ++j) Ov[i][j] = 0.f;
    }

    int kstart = q0 - W; if (kstart < 0) kstart = 0;
    kstart = (kstart >> 6) << 6;
    const float* kb_base = Kt + ((size_t)(b*NKV + kvh) * HDIM) * SEQ;
    const float* vb_base = V  + ((size_t)b * SEQ) * (NKV*HDIM) + kvh * HDIM;
    const float scale = 0.08838834764831845f;   // 1/sqrt(128)

    for (int k0 = kstart; k0 < q0 + 128; k0 += 64) {
        __syncthreads();   // previous iteration's Vs/Ps reads done
        // ---- load K tile [128 d][64 j] ----
#pragma unroll
        for (int r = 0; r < 8; ++r) {
            int id = tid + r*256;         // 0..2047
            int d  = id >> 4;
            int c4 = (id & 15) << 2;
            float4 v = *(const float4*)(kb_base + (size_t)d * SEQ + k0 + c4);
            *(float4*)(Ks + d*64 + c4) = v;
        }
        // ---- load V tile [64 j][128 d] ----
#pragma unroll
        for (int r = 0; r < 8; ++r) {
            int id = tid + r*256;
            int j  = id >> 5;
            int c4 = (id & 31) << 2;
            float4 v = *(const float4*)(vb_base + (size_t)(k0 + j) * (NKV*HDIM) + c4);
            *(float4*)(Vs + j*128 + c4) = v;
        }
        __syncthreads();

        // ---- S = Q K^T (each thread: 8 rows x 4 keys) ----
        float s[8][4];
#pragma unroll
        for (int i = 0; i < 8; ++i)
#pragma unroll
            for (int j = 0; j < 4; ++j) s[i][j] = 0.f;

#pragma unroll 4
        for (int kk = 0; kk < 128; ++kk) {
            float4 a0 = *(float4*)(Qs + kk*128 + ty*8);
            float4 a1 = *(float4*)(Qs + kk*128 + ty*8 + 4);
            float4 bk = *(float4*)(Ks + kk*64 + tx*4);
            float a[8] = {a0.x,a0.y,a0.z,a0.w,a1.x,a1.y,a1.z,a1.w};
            float bb[4] = {bk.x,bk.y,bk.z,bk.w};
#pragma unroll
            for (int i = 0; i < 8; ++i)
#pragma unroll
                for (int j = 0; j < 4; ++j)
                    s[i][j] += a[i] * bb[j];
        }

        // ---- mask + online softmax (rows reduced across 16 lanes) ----
        float alpha[8];
#pragma unroll
        for (int i = 0; i < 8; ++i) {
            int qi = q0 + ty*8 + i;
            float sv[4];
            float mx = -1.0e30f;
#pragma unroll
            for (int j = 0; j < 4; ++j) {
                int kj = k0 + tx*4 + j;
                int dist = qi - kj;
                float val = (dist >= 0 && dist <= W) ? s[i][j]*scale : -1.0e30f;
                sv[j] = val;
                mx = fmaxf(mx, val);
            }
#pragma unroll
            for (int off = 8; off; off >>= 1)
                mx = fmaxf(mx, __shfl_xor_sync(0xffffffffu, mx, off));
            float mnew = fmaxf(m_r[i], mx);
            float a = __expf(m_r[i] - mnew);
            bool dead = (mnew < -1.0e29f);
            float p[4], ls = 0.f;
#pragma unroll
            for (int j = 0; j < 4; ++j) {
                p[j] = dead ? 0.f : __expf(sv[j] - mnew);
                ls += p[j];
            }
#pragma unroll
            for (int off = 8; off; off >>= 1)
                ls += __shfl_xor_sync(0xffffffffu, ls, off);
            l_r[i] = l_r[i] * a + ls;
            m_r[i] = mnew;
            alpha[i] = a;
#pragma unroll
            for (int j = 0; j < 4; ++j)
                Ps[(tx*4 + j)*129 + ty*8 + i] = p[j];
        }
        __syncthreads();

        // ---- rescale O, then O += P V (each thread: 8 rows x 8 dims) ----
#pragma unroll
        for (int i = 0; i < 8; ++i)
#pragma unroll
            for (int j = 0; j < 8; ++j) Ov[i][j] *= alpha[i];

#pragma unroll 2
        for (int j = 0; j < 64; ++j) {
            float pf[8];
#pragma unroll
            for (int i = 0; i < 8; ++i) pf[i] = Ps[j*129 + ty*8 + i];
            float4 v0 = *(float4*)(Vs + j*128 + tx*8);
            float4 v1 = *(float4*)(Vs + j*128 + tx*8 + 4);
            float vv[8] = {v0.x,v0.y,v0.z,v0.w,v1.x,v1.y,v1.z,v1.w};
#pragma unroll
            for (int i = 0; i < 8; ++i)
#pragma unroll
                for (int jj = 0; jj < 8; ++jj)
                    Ov[i][jj] += pf[i] * vv[jj];
        }
    }

    // ---- epilogue: /l, * attn-gate, write Y[m][h*128+d] ----
#pragma unroll
    for (int i = 0; i < 8; ++i) {
        int row = b*SEQ + q0 + ty*8 + i;
        float g = AG[row*NHEAD + h];
        float inv = g / l_r[i];
        float* yp = Y + (size_t)row * EMBD + h*HDIM + tx*8;
        float4 o0 = make_float4(Ov[i][0]*inv, Ov[i][1]*inv, Ov[i][2]*inv, Ov[i][3]*inv);
        float4 o1 = make_float4(Ov[i][4]*inv, Ov[i][5]*inv, Ov[i][6]*inv, Ov[i][7]*inv);
        *(float4*)(yp)     = o0;
        *(float4*)(yp + 4) = o1;
    }
}

// ---------------------------------------------------------------------------
// Launch
// ---------------------------------------------------------------------------
extern "C" void kernel_launch(void* const* d_in, const int* in_sizes, int n_in,
                              void* d_out, int out_size)
{
    const float* x     = (const float*)d_in[0];
    const float* ve    = (const float*)d_in[1];
    const float* cosp  = (const float*)d_in[2];
    const float* sinp  = (const float*)d_in[3];
    const float* wq    = (const float*)d_in[4];
    const float* wk    = (const float*)d_in[5];
    const float* wv    = (const float*)d_in[6];
    const float* wproj = (const float*)d_in[7];
    const float* wg    = (const float*)d_in[8];
    const float* wa    = (const float*)d_in[9];
    const float* ps    = (const float*)d_in[10];
    const int*   wsz   = (n_in > 11) ? (const int*)d_in[11] : nullptr;

    float *Qraw, *Kraw, *Vb, *Qt, *Kt, *G, *AG, *Y;
    cudaGetSymbolAddress((void**)&Qraw, d_Qraw);
    cudaGetSymbolAddress((void**)&Kraw, d_Kraw);
    cudaGetSymbolAddress((void**)&Vb,   d_Vbuf);
    cudaGetSymbolAddress((void**)&Qt,   d_Qt);
    cudaGetSymbolAddress((void**)&Kt,   d_Kt);
    cudaGetSymbolAddress((void**)&G,    d_G);
    cudaGetSymbolAddress((void**)&AG,   d_AG);
    cudaGetSymbolAddress((void**)&Y,    d_Y);

    // 1-3: projections
    sgemm_kernel<<<dim3(EMBD/128, MROWS/128), 256>>>(x, wq, Qraw, MROWS, EMBD, EMBD, nullptr);
    sgemm_kernel<<<dim3((NKV*HDIM)/128, MROWS/128), 256>>>(x, wk, Kraw, MROWS, NKV*HDIM, EMBD, nullptr);
    sgemm_kernel<<<dim3((NKV*HDIM)/128, MROWS/128), 256>>>(x, wv, Vb,   MROWS, NKV*HDIM, EMBD, nullptr);

    // 4: gates
    gates_kernel<<<(MROWS*24 + 255)/256, 256>>>(x, wg, wa, G, AG);

    // 5: k-shift + rope + rmsnorm + v-gate
    post_kernel<<<(MROWS*32)/8, 256>>>(Qraw, Kraw, Vb, ve, cosp, sinp, G, Qt, Kt);

    // 6: attention
    cudaFuncSetAttribute(attn_kernel, cudaFuncAttributeMaxDynamicSharedMemorySize, ATTN_SMEM_BYTES);
    attn_kernel<<<dim3(SEQ/128, NHEAD, BATCH), 256, ATTN_SMEM_BYTES>>>(Qt, Kt, Vb, AG, Y, wsz);

    // 7: output projection with (1 + proj_scalar)
    sgemm_kernel<<<dim3(EMBD/128, MROWS/128), 256>>>(Y, wproj, (float*)d_out, MROWS, EMBD, EMBD, ps);
}

// round 4
// speedup vs baseline: 1.4862x; 1.4862x over previous
#include <cuda_runtime.h>
#include <cuda_bf16.h>
#include <cstdint>

// ---------------------------------------------------------------------------
// Problem constants (fixed by setup_inputs)
// ---------------------------------------------------------------------------
#define BATCH   2
#define SEQ     2048
#define MROWS   (BATCH*SEQ)      // 4096
#define EMBD    2048
#define NHEAD   16
#define NKV     8
#define HDIM    128
#define HALF    64

// ---------------------------------------------------------------------------
// Device scratch (no cudaMalloc allowed)
// ---------------------------------------------------------------------------
__device__ float d_Qraw[(size_t)MROWS*EMBD];
__device__ float d_Kraw[(size_t)MROWS*NKV*HDIM];
__device__ float d_Vbuf[(size_t)MROWS*NKV*HDIM];
__device__ float d_Qt[(size_t)BATCH*NHEAD*HDIM*SEQ];
__device__ float d_Kt[(size_t)BATCH*NKV*HDIM*SEQ];
__device__ float d_G[(size_t)MROWS*NKV];
__device__ float d_AG[(size_t)MROWS*NHEAD];
__device__ float d_Y[(size_t)MROWS*EMBD];

// ---------------------------------------------------------------------------
// Tensor-core GEMM (bf16x3 split, fp32 accuracy-class):
//   C[M,N] = A[M,K] @ B[K,N]  (row-major), optional (1+s) epilogue scale
// CTA 128x128x32, 8 warps (2x4), warp tile 64x32, mma.m16n8k16.bf16
// ---------------------------------------------------------------------------
#define GBM 128
#define GBN 128
#define GBK 32
#define ASTR 40     // bf16 stride for A smem rows (conflict-free ldmatrix)
#define BSTR 136    // bf16 stride for B smem rows

__device__ __forceinline__ uint32_t smem_u32(const void* p) {
    return (uint32_t)__cvta_generic_to_shared(p);
}
__device__ __forceinline__ void ldsm_x4(uint32_t* r, uint32_t addr) {
    asm volatile("ldmatrix.sync.aligned.m8n8.x4.shared.b16 {%0,%1,%2,%3}, [%4];"
        : "=r"(r[0]), "=r"(r[1]), "=r"(r[2]), "=r"(r[3]) : "r"(addr));
}
__device__ __forceinline__ void ldsm_x4_t(uint32_t* r, uint32_t addr) {
    asm volatile("ldmatrix.sync.aligned.m8n8.x4.trans.shared.b16 {%0,%1,%2,%3}, [%4];"
        : "=r"(r[0]), "=r"(r[1]), "=r"(r[2]), "=r"(r[3]) : "r"(addr));
}
__device__ __forceinline__ void mma16816(float* c, const uint32_t* a, const uint32_t* b) {
    asm volatile(
        "mma.sync.aligned.m16n8k16.row.col.f32.bf16.bf16.f32 "
        "{%0,%1,%2,%3}, {%4,%5,%6,%7}, {%8,%9}, {%0,%1,%2,%3};"
        : "+f"(c[0]), "+f"(c[1]), "+f"(c[2]), "+f"(c[3])
        : "r"(a[0]), "r"(a[1]), "r"(a[2]), "r"(a[3]), "r"(b[0]), "r"(b[1]));
}
// split two floats into packed-bf16 (hi pair, lo pair)
__device__ __forceinline__ void split2(float v0, float v1, uint32_t& hi, uint32_t& lo) {
    __nv_bfloat16 h0 = __float2bfloat16_rn(v0);
    __nv_bfloat16 h1 = __float2bfloat16_rn(v1);
    __nv_bfloat16 l0 = __float2bfloat16_rn(v0 - __bfloat162float(h0));
    __nv_bfloat16 l1 = __float2bfloat16_rn(v1 - __bfloat162float(h1));
    hi = (uint32_t)(*(uint16_t*)&h0) | ((uint32_t)(*(uint16_t*)&h1) << 16);
    lo = (uint32_t)(*(uint16_t*)&l0) | ((uint32_t)(*(uint16_t*)&l1) << 16);
}

__global__ void __launch_bounds__(256, 1) gemm_tc_kernel(
    const float* __restrict__ A, const float* __restrict__ B,
    float* __restrict__ C, int M, int N, int K,
    const float* __restrict__ scale_ptr)
{
    __shared__ __nv_bfloat16 Ah[GBM*ASTR];
    __shared__ __nv_bfloat16 Al[GBM*ASTR];
    __shared__ __nv_bfloat16 Bh[GBK*BSTR];
    __shared__ __nv_bfloat16 Bl[GBK*BSTR];

    const int tid  = threadIdx.x;
    const int warp = tid >> 5, lane = tid & 31;
    const int wm = warp >> 2, wn = warp & 3;       // warp grid 2(m) x 4(n)
    const int m0 = blockIdx.y * GBM, n0 = blockIdx.x * GBN;

    // global load indices (register-staged)
    const int arow = tid >> 3, acol = (tid & 7) * 4;    // rows += p*32
    const int brow = tid >> 5, bcol = (tid & 31) * 4;   // rows += p*8

    float4 ra[4], rb[4];

    // --- prologue: load tile 0, convert, store ---
#pragma unroll
    for (int p = 0; p < 4; ++p)
        ra[p] = *(const float4*)(A + (size_t)(m0 + p*32 + arow) * K + acol);
#pragma unroll
    for (int p = 0; p < 4; ++p)
        rb[p] = *(const float4*)(B + (size_t)(p*8 + brow) * N + n0 + bcol);
#pragma unroll
    for (int p = 0; p < 4; ++p) {
        uint32_t h01, l01, h23, l23;
        split2(ra[p].x, ra[p].y, h01, l01);
        split2(ra[p].z, ra[p].w, h23, l23);
        int off = (p*32 + arow) * ASTR + acol;
        *(uint2*)&Ah[off] = make_uint2(h01, h23);
        *(uint2*)&Al[off] = make_uint2(l01, l23);
        split2(rb[p].x, rb[p].y, h01, l01);
        split2(rb[p].z, rb[p].w, h23, l23);
        off = (p*8 + brow) * BSTR + bcol;
        *(uint2*)&Bh[off] = make_uint2(h01, h23);
        *(uint2*)&Bl[off] = make_uint2(l01, l23);
    }
    __syncthreads();

    float acc[4][4][4];
#pragma unroll
    for (int im = 0; im < 4; ++im)
#pragma unroll
        for (int in_ = 0; in_ < 4; ++in_)
#pragma unroll
            for (int r = 0; r < 4; ++r) acc[im][in_][r] = 0.f;

    // per-lane ldmatrix offsets
    const uint32_t ah_base = smem_u32(Ah), al_base = smem_u32(Al);
    const uint32_t bh_base = smem_u32(Bh), bl_base = smem_u32(Bl);
    const int a_lrow  = wm*64 + (lane & 15);
    const int a_lcolh = (lane >> 4) * 8;
    const int b_lrow  = (lane & 15);
    const int b_lcol  = wn*32 + (lane >> 4) * 8;

    for (int k0 = 0; k0 < K; k0 += GBK) {
        const bool notlast = (k0 + GBK) < K;
        if (notlast) {
#pragma unroll
            for (int p = 0; p < 4; ++p)
                ra[p] = *(const float4*)(A + (size_t)(m0 + p*32 + arow) * K + (k0 + GBK) + acol);
#pragma unroll
            for (int p = 0; p < 4; ++p)
                rb[p] = *(const float4*)(B + (size_t)(k0 + GBK + p*8 + brow) * N + n0 + bcol);
        }

#pragma unroll
        for (int ks = 0; ks < GBK; ks += 16) {
            uint32_t ah[4][4], alr[4][4], bh[2][4], blr[2][4];
#pragma unroll
            for (int im = 0; im < 4; ++im) {
                uint32_t off = (uint32_t)(((a_lrow + im*16) * ASTR + ks + a_lcolh) * 2);
                ldsm_x4(ah[im],  ah_base + off);
                ldsm_x4(alr[im], al_base + off);
            }
#pragma unroll
            for (int pr = 0; pr < 2; ++pr) {
                uint32_t off = (uint32_t)(((ks + b_lrow) * BSTR + b_lcol + pr*16) * 2);
                ldsm_x4_t(bh[pr],  bh_base + off);
                ldsm_x4_t(blr[pr], bl_base + off);
            }
#pragma unroll
            for (int im = 0; im < 4; ++im)
#pragma unroll
                for (int in_ = 0; in_ < 4; ++in_) {
                    const uint32_t* bhp = &bh[in_ >> 1][(in_ & 1) * 2];
                    const uint32_t* blp = &blr[in_ >> 1][(in_ & 1) * 2];
                    mma16816(acc[im][in_], ah[im],  bhp);   // hi*hi
                    mma16816(acc[im][in_], alr[im], bhp);   // lo*hi
                    mma16816(acc[im][in_], ah[im],  blp);   // hi*lo
                }
        }

        if (notlast) {
            __syncthreads();
#pragma unroll
            for (int p = 0; p < 4; ++p) {
                uint32_t h01, l01, h23, l23;
                split2(ra[p].x, ra[p].y, h01, l01);
                split2(ra[p].z, ra[p].w, h23, l23);
                int off = (p*32 + arow) * ASTR + acol;
                *(uint2*)&Ah[off] = make_uint2(h01, h23);
                *(uint2*)&Al[off] = make_uint2(l01, l23);
                split2(rb[p].x, rb[p].y, h01, l01);
                split2(rb[p].z, rb[p].w, h23, l23);
                off = (p*8 + brow) * BSTR + bcol;
                *(uint2*)&Bh[off] = make_uint2(h01, h23);
                *(uint2*)&Bl[off] = make_uint2(l01, l23);
            }
            __syncthreads();
        }
    }

    // --- epilogue ---
    float scl = 1.0f;
    if (scale_ptr) scl = 1.0f + scale_ptr[0];
    const int g = lane >> 2, t4 = lane & 3;
#pragma unroll
    for (int im = 0; im < 4; ++im)
#pragma unroll
        for (int in_ = 0; in_ < 4; ++in_) {
            int r = m0 + wm*64 + im*16 + g;
            int c = n0 + wn*32 + in_*8 + 2*t4;
            *(float2*)(C + (size_t)r * N + c) =
                make_float2(acc[im][in_][0]*scl, acc[im][in_][1]*scl);
            *(float2*)(C + (size_t)(r + 8) * N + c) =
                make_float2(acc[im][in_][2]*scl, acc[im][in_][3]*scl);
        }
}

// ---------------------------------------------------------------------------
// Gates: G[m][kvh] = 2*sigmoid(x[m,:32] @ w_ve_gate[:,kvh])
//        AG[m][h]  =   sigmoid(x[m,:12] @ w_attn_gate[:,h])
// ---------------------------------------------------------------------------
__global__ void gates_kernel(const float* __restrict__ x,
                             const float* __restrict__ wg,
                             const float* __restrict__ wa,
                             float* __restrict__ G, float* __restrict__ AG)
{
    int job = blockIdx.x * blockDim.x + threadIdx.x;
    if (job >= MROWS * 24) return;
    int m = job / 24;
    int s = job - m * 24;
    const float* xr = x + (size_t)m * EMBD;
    if (s < 8) {
        float acc = 0.f;
#pragma unroll
        for (int c = 0; c < 32; ++c) acc += xr[c] * wg[c*8 + s];
        G[m*8 + s] = 2.0f / (1.0f + __expf(-acc));
    } else {
        int h = s - 8;
        float acc = 0.f;
#pragma unroll
        for (int c = 0; c < 12; ++c) acc += xr[c] * wa[c*16 + h];
        AG[m*16 + h] = 1.0f / (1.0f + __expf(-acc));
    }
}

// ---------------------------------------------------------------------------
// Post: k-shift + RoPE + RMSNorm for q,k (written d-major [b][head][d][t]);
//       v += gate * ve (in place).
// ---------------------------------------------------------------------------
__global__ void post_kernel(const float* __restrict__ Qraw,
                            const float* __restrict__ Kraw,
                            float* __restrict__ Vb,
                            const float* __restrict__ ve,
                            const float* __restrict__ cosp,
                            const float* __restrict__ sinp,
                            const float* __restrict__ G,
                            float* __restrict__ Qt,
                            float* __restrict__ Kt)
{
    int gw   = (blockIdx.x * blockDim.x + threadIdx.x) >> 5;
    int lane = threadIdx.x & 31;
    int m    = gw >> 5;
    int slot = gw & 31;
    int b = m >> 11;
    int t = m & (SEQ - 1);

    if (slot < 24) {
        float r0, r1, r2, r3;
        float* dst;
        if (slot < 16) {
            int h = slot;
            const float* base = Qraw + (size_t)m * EMBD + h * HDIM;
            r0 = base[lane];      r1 = base[lane + 32];
            r2 = base[lane + 64]; r3 = base[lane + 96];
            dst = Qt + ((size_t)(b*NHEAD + h) * HDIM) * SEQ + t;
        } else {
            int kvh = slot - 16;
            int mprev = (t > 0) ? (m - 1) : m;
            const float* bl = Kraw + (size_t)m     * (NKV*HDIM) + kvh * HDIM;
            const float* bu = Kraw + (size_t)mprev * (NKV*HDIM) + kvh * HDIM;
            r0 = bl[lane];      r1 = bl[lane + 32];
            r2 = bu[lane + 64]; r3 = bu[lane + 96];
            dst = Kt + ((size_t)(b*NKV + kvh) * HDIM) * SEQ + t;
        }
        float c0 = cosp[t*HALF + lane], c1 = cosp[t*HALF + lane + 32];
        float s0 = sinp[t*HALF + lane], s1 = sinp[t*HALF + lane + 32];
        float o0 = r0*c0 + r2*s0;
        float o1 = r1*c1 + r3*s1;
        float o2 = r2*c0 - r0*s0;
        float o3 = r3*c1 - r1*s1;
        float ss = o0*o0 + o1*o1 + o2*o2 + o3*o3;
#pragma unroll
        for (int off = 16; off; off >>= 1)
            ss += __shfl_xor_sync(0xffffffffu, ss, off);
        float rn = rsqrtf(ss * (1.0f/128.0f) + 1.1920929e-7f);
        dst[(size_t)lane        * SEQ] = o0 * rn;
        dst[(size_t)(lane + 32) * SEQ] = o1 * rn;
        dst[(size_t)(lane + 64) * SEQ] = o2 * rn;
        dst[(size_t)(lane + 96) * SEQ] = o3 * rn;
    } else {
        int kvh = slot - 24;
        float g = G[m*8 + kvh];
        size_t off = (size_t)m * (NKV*HDIM) + kvh * HDIM;
#pragma unroll
        for (int d = lane; d < HDIM; d += 32)
            Vb[off + d] = Vb[off + d] + g * ve[off + d];
    }
}

// ---------------------------------------------------------------------------
// Flash attention, fp32, sliding window (0 <= dist <= W).
// ---------------------------------------------------------------------------
#define ATTN_SMEM_FLOATS (128*128 + 128*64 + 64*128 + 64*129)
#define ATTN_SMEM_BYTES  (ATTN_SMEM_FLOATS * 4)

__global__ void __launch_bounds__(256, 1) attn_kernel(
    const float* __restrict__ Qt, const float* __restrict__ Kt,
    const float* __restrict__ V,  const float* __restrict__ AG,
    float* __restrict__ Y, const int* __restrict__ wptr)
{
    extern __shared__ float sm[];
    float* Qs = sm;
    float* Ks = Qs + 128*128;
    float* Vs = Ks + 128*64;
    float* Ps = Vs + 64*128;

    const int tid = threadIdx.x;
    const int tx = tid & 15;
    const int ty = tid >> 4;
    const int qb = blockIdx.x, h = blockIdx.y, b = blockIdx.z;
    const int kvh = h >> 1;
    const int q0 = qb * 128;

    int W = 1024;
    if (wptr) {
        int iv = wptr[0];
        if (iv > 0 && iv < (1 << 20)) W = iv;
        else {
            float fv = __int_as_float(iv);
            if (fv > 0.f && fv < 1.0e6f) W = (int)fv;
        }
    }

    const float* qbase = Qt + ((size_t)(b*NHEAD + h) * HDIM) * SEQ + q0;
#pragma unroll
    for (int r = 0; r < 16; ++r) {
        int id = tid + r*256;
        int d  = id >> 5;
        int c4 = (id & 31) << 2;
        float4 v = *(const float4*)(qbase + (size_t)d * SEQ + c4);
        *(float4*)(Qs + d*128 + c4) = v;
    }

    float m_r[8], l_r[8], Ov[8][8];
#pragma unroll
    for (int i = 0; i < 8; ++i) {
        m_r[i] = -1.0e30f; l_r[i] = 0.f;
#pragma unroll
        for (int j = 0; j < 8; ++j) Ov[i][j] = 0.f;
    }

    int kstart = q0 - W; if (kstart < 0) kstart = 0;
    kstart = (kstart >> 6) << 6;
    const float* kb_base = Kt + ((size_t)(b*NKV + kvh) * HDIM) * SEQ;
    const float* vb_base = V  + ((size_t)b * SEQ) * (NKV*HDIM) + kvh * HDIM;
    const float scale = 0.08838834764831845f;

    for (int k0 = kstart; k0 < q0 + 128; k0 += 64) {
        __syncthreads();
#pragma unroll
        for (int r = 0; r < 8; ++r) {
            int id = tid + r*256;
            int d  = id >> 4;
            int c4 = (id & 15) << 2;
            float4 v = *(const float4*)(kb_base + (size_t)d * SEQ + k0 + c4);
            *(float4*)(Ks + d*64 + c4) = v;
        }
#pragma unroll
        for (int r = 0; r < 8; ++r) {
            int id = tid + r*256;
            int j  = id >> 5;
            int c4 = (id & 31) << 2;
            float4 v = *(const float4*)(vb_base + (size_t)(k0 + j) * (NKV*HDIM) + c4);
            *(float4*)(Vs + j*128 + c4) = v;
        }
        __syncthreads();

        float s[8][4];
#pragma unroll
        for (int i = 0; i < 8; ++i)
#pragma unroll
            for (int j = 0; j < 4; ++j) s[i][j] = 0.f;

#pragma unroll 4
        for (int kk = 0; kk < 128; ++kk) {
            float4 a0 = *(float4*)(Qs + kk*128 + ty*8);
            float4 a1 = *(float4*)(Qs + kk*128 + ty*8 + 4);
            float4 bk = *(float4*)(Ks + kk*64 + tx*4);
            float a[8] = {a0.x,a0.y,a0.z,a0.w,a1.x,a1.y,a1.z,a1.w};
            float bb[4] = {bk.x,bk.y,bk.z,bk.w};
#pragma unroll
            for (int i = 0; i < 8; ++i)
#pragma unroll
                for (int j = 0; j < 4; ++j)
                    s[i][j] += a[i] * bb[j];
        }

        float alpha[8];
#pragma unroll
        for (int i = 0; i < 8; ++i) {
            int qi = q0 + ty*8 + i;
            float sv[4];
            float mx = -1.0e30f;
#pragma unroll
            for (int j = 0; j < 4; ++j) {
                int kj = k0 + tx*4 + j;
                int dist = qi - kj;
                float val = (dist >= 0 && dist <= W) ? s[i][j]*scale : -1.0e30f;
                sv[j] = val;
                mx = fmaxf(mx, val);
            }
#pragma unroll
            for (int off = 8; off; off >>= 1)
                mx = fmaxf(mx, __shfl_xor_sync(0xffffffffu, mx, off));
            float mnew = fmaxf(m_r[i], mx);
            float a = __expf(m_r[i] - mnew);
            bool dead = (mnew < -1.0e29f);
            float p[4], ls = 0.f;
#pragma unroll
            for (int j = 0; j < 4; ++j) {
                p[j] = dead ? 0.f : __expf(sv[j] - mnew);
                ls += p[j];
            }
#pragma unroll
            for (int off = 8; off; off >>= 1)
                ls += __shfl_xor_sync(0xffffffffu, ls, off);
            l_r[i] = l_r[i] * a + ls;
            m_r[i] = mnew;
            alpha[i] = a;
#pragma unroll
            for (int j = 0; j < 4; ++j)
                Ps[(tx*4 + j)*129 + ty*8 + i] = p[j];
        }
        __syncthreads();

#pragma unroll
        for (int i = 0; i < 8; ++i)
#pragma unroll
            for (int j = 0; j < 8; ++j) Ov[i][j] *= alpha[i];

#pragma unroll 2
        for (int j = 0; j < 64; ++j) {
            float pf[8];
#pragma unroll
            for (int i = 0; i < 8; ++i) pf[i] = Ps[j*129 + ty*8 + i];
            float4 v0 = *(float4*)(Vs + j*128 + tx*8);
            float4 v1 = *(float4*)(Vs + j*128 + tx*8 + 4);
            float vv[8] = {v0.x,v0.y,v0.z,v0.w,v1.x,v1.y,v1.z,v1.w};
#pragma unroll
            for (int i = 0; i < 8; ++i)
#pragma unroll
                for (int jj = 0; jj < 8; ++jj)
                    Ov[i][jj] += pf[i] * vv[jj];
        }
    }

#pragma unroll
    for (int i = 0; i < 8; ++i) {
        int row = b*SEQ + q0 + ty*8 + i;
        float g = AG[row*NHEAD + h];
        float inv = g / l_r[i];
        float* yp = Y + (size_t)row * EMBD + h*HDIM + tx*8;
        float4 o0 = make_float4(Ov[i][0]*inv, Ov[i][1]*inv, Ov[i][2]*inv, Ov[i][3]*inv);
        float4 o1 = make_float4(Ov[i][4]*inv, Ov[i][5]*inv, Ov[i][6]*inv, Ov[i][7]*inv);
        *(float4*)(yp)     = o0;
        *(float4*)(yp + 4) = o1;
    }
}

// ---------------------------------------------------------------------------
// Launch
// ---------------------------------------------------------------------------
extern "C" void kernel_launch(void* const* d_in, const int* in_sizes, int n_in,
                              void* d_out, int out_size)
{
    const float* x     = (const float*)d_in[0];
    const float* ve    = (const float*)d_in[1];
    const float* cosp  = (const float*)d_in[2];
    const float* sinp  = (const float*)d_in[3];
    const float* wq    = (const float*)d_in[4];
    const float* wk    = (const float*)d_in[5];
    const float* wv    = (const float*)d_in[6];
    const float* wproj = (const float*)d_in[7];
    const float* wg    = (const float*)d_in[8];
    const float* wa    = (const float*)d_in[9];
    const float* ps    = (const float*)d_in[10];
    const int*   wsz   = (n_in > 11) ? (const int*)d_in[11] : nullptr;

    float *Qraw, *Kraw, *Vb, *Qt, *Kt, *G, *AG, *Y;
    cudaGetSymbolAddress((void**)&Qraw, d_Qraw);
    cudaGetSymbolAddress((void**)&Kraw, d_Kraw);
    cudaGetSymbolAddress((void**)&Vb,   d_Vbuf);
    cudaGetSymbolAddress((void**)&Qt,   d_Qt);
    cudaGetSymbolAddress((void**)&Kt,   d_Kt);
    cudaGetSymbolAddress((void**)&G,    d_G);
    cudaGetSymbolAddress((void**)&AG,   d_AG);
    cudaGetSymbolAddress((void**)&Y,    d_Y);

    // 1-3: projections (tensor core)
    gemm_tc_kernel<<<dim3(EMBD/GBN, MROWS/GBM), 256>>>(x, wq, Qraw, MROWS, EMBD, EMBD, nullptr);
    gemm_tc_kernel<<<dim3((NKV*HDIM)/GBN, MROWS/GBM), 256>>>(x, wk, Kraw, MROWS, NKV*HDIM, EMBD, nullptr);
    gemm_tc_kernel<<<dim3((NKV*HDIM)/GBN, MROWS/GBM), 256>>>(x, wv, Vb,   MROWS, NKV*HDIM, EMBD, nullptr);

    // 4: gates
    gates_kernel<<<(MROWS*24 + 255)/256, 256>>>(x, wg, wa, G, AG);

    // 5: k-shift + rope + rmsnorm + v-gate
    post_kernel<<<(MROWS*32)/8, 256>>>(Qraw, Kraw, Vb, ve, cosp, sinp, G, Qt, Kt);

    // 6: attention
    cudaFuncSetAttribute(attn_kernel, cudaFuncAttributeMaxDynamicSharedMemorySize, ATTN_SMEM_BYTES);
    attn_kernel<<<dim3(SEQ/128, NHEAD, BATCH), 256, ATTN_SMEM_BYTES>>>(Qt, Kt, Vb, AG, Y, wsz);

    // 7: output projection with (1 + proj_scalar)
    gemm_tc_kernel<<<dim3(EMBD/GBN, MROWS/GBM), 256>>>(Y, wproj, (float*)d_out, MROWS, EMBD, EMBD, ps);
}

// round 6
// speedup vs baseline: 2.3394x; 1.5741x over previous
#include <cuda_runtime.h>
#include <cuda_bf16.h>
#include <cstdint>

// ---------------------------------------------------------------------------
// Problem constants
// ---------------------------------------------------------------------------
#define BATCH   2
#define SEQ     2048
#define MROWS   (BATCH*SEQ)      // 4096
#define EMBD    2048
#define NHEAD   16
#define NKV     8
#define HDIM    128
#define HALF    64
#define KVDIM   (NKV*HDIM)       // 1024

// ---------------------------------------------------------------------------
// Device scratch
// ---------------------------------------------------------------------------
__device__ float d_Qraw[(size_t)MROWS*EMBD];
__device__ float d_Kraw[(size_t)MROWS*KVDIM];
__device__ float d_Vraw[(size_t)MROWS*KVDIM];
__device__ float d_G[(size_t)MROWS*NKV];
__device__ float d_AG[(size_t)MROWS*NHEAD];

__device__ __nv_bfloat16 d_Xh[(size_t)MROWS*EMBD],  d_Xl[(size_t)MROWS*EMBD];
__device__ __nv_bfloat16 d_Wqh[(size_t)EMBD*EMBD],  d_Wql[(size_t)EMBD*EMBD];
__device__ __nv_bfloat16 d_Wkh[(size_t)EMBD*KVDIM], d_Wkl[(size_t)EMBD*KVDIM];
__device__ __nv_bfloat16 d_Wvh[(size_t)EMBD*KVDIM], d_Wvl[(size_t)EMBD*KVDIM];
__device__ __nv_bfloat16 d_Wph[(size_t)EMBD*EMBD],  d_Wpl[(size_t)EMBD*EMBD];

__device__ __nv_bfloat16 d_Qbh[(size_t)MROWS*EMBD],  d_Qbl[(size_t)MROWS*EMBD];   // [b][h][t][d]
__device__ __nv_bfloat16 d_Kbh[(size_t)MROWS*KVDIM], d_Kbl[(size_t)MROWS*KVDIM];  // [b][kvh][t][d]
__device__ __nv_bfloat16 d_Vbh[(size_t)MROWS*KVDIM], d_Vbl[(size_t)MROWS*KVDIM];  // [b][kvh][t][d]
__device__ __nv_bfloat16 d_Yh[(size_t)MROWS*EMBD],   d_Yl[(size_t)MROWS*EMBD];

// ---------------------------------------------------------------------------
// Helpers
// ---------------------------------------------------------------------------
__device__ __forceinline__ uint32_t smem_u32(const void* p) {
    return (uint32_t)__cvta_generic_to_shared(p);
}
__device__ __forceinline__ void ldsm_x4(uint32_t* r, uint32_t addr) {
    asm volatile("ldmatrix.sync.aligned.m8n8.x4.shared.b16 {%0,%1,%2,%3}, [%4];"
        : "=r"(r[0]), "=r"(r[1]), "=r"(r[2]), "=r"(r[3]) : "r"(addr));
}
__device__ __forceinline__ void ldsm_x4_t(uint32_t* r, uint32_t addr) {
    asm volatile("ldmatrix.sync.aligned.m8n8.x4.trans.shared.b16 {%0,%1,%2,%3}, [%4];"
        : "=r"(r[0]), "=r"(r[1]), "=r"(r[2]), "=r"(r[3]) : "r"(addr));
}
__device__ __forceinline__ void mma16816(float* c, const uint32_t* a, const uint32_t* b) {
    asm volatile(
        "mma.sync.aligned.m16n8k16.row.col.f32.bf16.bf16.f32 "
        "{%0,%1,%2,%3}, {%4,%5,%6,%7}, {%8,%9}, {%0,%1,%2,%3};"
        : "+f"(c[0]), "+f"(c[1]), "+f"(c[2]), "+f"(c[3])
        : "r"(a[0]), "r"(a[1]), "r"(a[2]), "r"(a[3]), "r"(b[0]), "r"(b[1]));
}
__device__ __forceinline__ void split2(float v0, float v1, uint32_t& hi, uint32_t& lo) {
    __nv_bfloat16 h0 = __float2bfloat16_rn(v0);
    __nv_bfloat16 h1 = __float2bfloat16_rn(v1);
    __nv_bfloat16 l0 = __float2bfloat16_rn(v0 - __bfloat162float(h0));
    __nv_bfloat16 l1 = __float2bfloat16_rn(v1 - __bfloat162float(h1));
    hi = (uint32_t)(*(uint16_t*)&h0) | ((uint32_t)(*(uint16_t*)&h1) << 16);
    lo = (uint32_t)(*(uint16_t*)&l0) | ((uint32_t)(*(uint16_t*)&l1) << 16);
}
__device__ __forceinline__ void split1(float v, __nv_bfloat16& h, __nv_bfloat16& l) {
    h = __float2bfloat16_rn(v);
    l = __float2bfloat16_rn(v - __bfloat162float(h));
}
#define CP16(dst_u32, src_ptr) \
    asm volatile("cp.async.cg.shared.global [%0], [%1], 16;" :: "r"(dst_u32), "l"(src_ptr))
__device__ __forceinline__ void cp_commit() { asm volatile("cp.async.commit_group;"); }
__device__ __forceinline__ void cp_wait1()  { asm volatile("cp.async.wait_group 1;"); }
__device__ __forceinline__ void cp_wait0()  { asm volatile("cp.async.wait_group 0;"); }

// ---------------------------------------------------------------------------
// Split kernel: fp32 -> (hi, lo) bf16
// ---------------------------------------------------------------------------
__global__ void split_kernel(const float* __restrict__ src,
                             __nv_bfloat16* __restrict__ hi,
                             __nv_bfloat16* __restrict__ lo, int n4)
{
    int i = blockIdx.x * blockDim.x + threadIdx.x;
    if (i >= n4) return;
    float4 v = ((const float4*)src)[i];
    uint32_t h01, l01, h23, l23;
    split2(v.x, v.y, h01, l01);
    split2(v.z, v.w, h23, l23);
    ((uint2*)hi)[i] = make_uint2(h01, h23);
    ((uint2*)lo)[i] = make_uint2(l01, l23);
}

// ---------------------------------------------------------------------------
// bf16x3 GEMM, pre-split operands, cp.async double-buffered.
//   C[M,N] fp32 = (Ah+Al)[M,K] @ (Bh+Bl)[K,N], optional (1+s) scale
// CTA 128x128x32, 8 warps (2m x 4n), warp tile 64x32
// ---------------------------------------------------------------------------
#define ASTR 40
#define BSTR 136
#define AS_ELEM (128*ASTR)      // 5120
#define BS_ELEM (32*BSTR)       // 4352
#define STG_ELEM (2*AS_ELEM + 2*BS_ELEM)   // 18944
#define GEMM_SMEM_BYTES (2*STG_ELEM*2)     // 75776

__global__ void __launch_bounds__(256, 1) gemm_bf16x3_kernel(
    const __nv_bfloat16* __restrict__ Ah, const __nv_bfloat16* __restrict__ Al,
    const __nv_bfloat16* __restrict__ Bh, const __nv_bfloat16* __restrict__ Bl,
    float* __restrict__ C, int M, int N, int K,
    const float* __restrict__ scale_ptr)
{
    extern __shared__ __nv_bfloat16 sg[];

    const int tid  = threadIdx.x;
    const int warp = tid >> 5, lane = tid & 31;
    const int wm = warp >> 2, wn = warp & 3;
    const int m0 = blockIdx.y * 128, n0 = blockIdx.x * 128;

    auto issue = [&](int k0, int s) {
        __nv_bfloat16* dAh = sg + s*STG_ELEM;
        __nv_bfloat16* dAl = dAh + AS_ELEM;
        __nv_bfloat16* dBh = dAl + AS_ELEM;
        __nv_bfloat16* dBl = dBh + BS_ELEM;
#pragma unroll
        for (int r = 0; r < 2; ++r) {
            int c   = tid + r*256;
            int row = c >> 2, col = (c & 3) * 8;
            size_t so = (size_t)(m0 + row) * K + k0 + col;
            CP16(smem_u32(dAh + row*ASTR + col), Ah + so);
            CP16(smem_u32(dAl + row*ASTR + col), Al + so);
        }
#pragma unroll
        for (int r = 0; r < 2; ++r) {
            int c   = tid + r*256;
            int row = c >> 4, col = (c & 15) * 8;
            size_t so = (size_t)(k0 + row) * N + n0 + col;
            CP16(smem_u32(dBh + row*BSTR + col), Bh + so);
            CP16(smem_u32(dBl + row*BSTR + col), Bl + so);
        }
        cp_commit();
    };

    float acc[4][4][4];
#pragma unroll
    for (int im = 0; im < 4; ++im)
#pragma unroll
        for (int in_ = 0; in_ < 4; ++in_)
#pragma unroll
            for (int r = 0; r < 4; ++r) acc[im][in_][r] = 0.f;

    const int a_lrow  = wm*64 + (lane & 15);
    const int a_lcolh = (lane >> 4) * 8;
    const int b_lrow  = (lane & 15);
    const int b_lcol  = wn*32 + (lane >> 4) * 8;

    const int nt = K / 32;
    issue(0, 0);

    for (int i = 0; i < nt; ++i) {
        if (i + 1 < nt) { issue((i+1)*32, (i+1) & 1); cp_wait1(); }
        else            { cp_wait0(); }
        __syncthreads();

        const __nv_bfloat16* sAh = sg + (i & 1)*STG_ELEM;
        const __nv_bfloat16* sAl = sAh + AS_ELEM;
        const __nv_bfloat16* sBh = sAl + AS_ELEM;
        const __nv_bfloat16* sBl = sBh + BS_ELEM;
        const uint32_t ah_base = smem_u32(sAh), al_base = smem_u32(sAl);
        const uint32_t bh_base = smem_u32(sBh), bl_base = smem_u32(sBl);

#pragma unroll
        for (int ks = 0; ks < 32; ks += 16) {
            uint32_t ah[4][4], alr[4][4], bh[2][4], blr[2][4];
#pragma unroll
            for (int im = 0; im < 4; ++im) {
                uint32_t off = (uint32_t)(((a_lrow + im*16) * ASTR + ks + a_lcolh) * 2);
                ldsm_x4(ah[im],  ah_base + off);
                ldsm_x4(alr[im], al_base + off);
            }
#pragma unroll
            for (int pr = 0; pr < 2; ++pr) {
                uint32_t off = (uint32_t)(((ks + b_lrow) * BSTR + b_lcol + pr*16) * 2);
                ldsm_x4_t(bh[pr],  bh_base + off);
                ldsm_x4_t(blr[pr], bl_base + off);
            }
#pragma unroll
            for (int im = 0; im < 4; ++im)
#pragma unroll
                for (int in_ = 0; in_ < 4; ++in_) {
                    const uint32_t* bhp = &bh[in_ >> 1][(in_ & 1) * 2];
                    const uint32_t* blp = &blr[in_ >> 1][(in_ & 1) * 2];
                    mma16816(acc[im][in_], ah[im],  bhp);
                    mma16816(acc[im][in_], alr[im], bhp);
                    mma16816(acc[im][in_], ah[im],  blp);
                }
        }
        __syncthreads();
    }

    float scl = 1.0f;
    if (scale_ptr) scl = 1.0f + scale_ptr[0];
    const int g = lane >> 2, t4 = lane & 3;
#pragma unroll
    for (int im = 0; im < 4; ++im)
#pragma unroll
        for (int in_ = 0; in_ < 4; ++in_) {
            int r = m0 + wm*64 + im*16 + g;
            int c = n0 + wn*32 + in_*8 + 2*t4;
            *(float2*)(C + (size_t)r * N + c) =
                make_float2(acc[im][in_][0]*scl, acc[im][in_][1]*scl);
            *(float2*)(C + (size_t)(r + 8) * N + c) =
                make_float2(acc[im][in_][2]*scl, acc[im][in_][3]*scl);
        }
}

// ---------------------------------------------------------------------------
// Gates
// ---------------------------------------------------------------------------
__global__ void gates_kernel(const float* __restrict__ x,
                             const float* __restrict__ wg,
                             const float* __restrict__ wa,
                             float* __restrict__ G, float* __restrict__ AG)
{
    int job = blockIdx.x * blockDim.x + threadIdx.x;
    if (job >= MROWS * 24) return;
    int m = job / 24;
    int s = job - m * 24;
    const float* xr = x + (size_t)m * EMBD;
    if (s < 8) {
        float acc = 0.f;
#pragma unroll
        for (int c = 0; c < 32; ++c) acc += xr[c] * wg[c*8 + s];
        G[m*8 + s] = 2.0f / (1.0f + __expf(-acc));
    } else {
        int h = s - 8;
        float acc = 0.f;
#pragma unroll
        for (int c = 0; c < 12; ++c) acc += xr[c] * wa[c*16 + h];
        AG[m*16 + h] = 1.0f / (1.0f + __expf(-acc));
    }
}

// ---------------------------------------------------------------------------
// Post: k-shift + RoPE + RMSNorm for q,k -> bf16 hi/lo [b][head][t][d]
//       (q has 1/sqrt(D) folded in); v = v + g*ve -> bf16 hi/lo
// ---------------------------------------------------------------------------
#define QK_SCALE 0.08838834764831845f

__global__ void post_kernel(const float* __restrict__ Qraw,
                            const float* __restrict__ Kraw,
                            const float* __restrict__ Vraw,
                            const float* __restrict__ ve,
                            const float* __restrict__ cosp,
                            const float* __restrict__ sinp,
                            const float* __restrict__ G,
                            __nv_bfloat16* __restrict__ Qh, __nv_bfloat16* __restrict__ Ql,
                            __nv_bfloat16* __restrict__ Kh, __nv_bfloat16* __restrict__ Kl,
                            __nv_bfloat16* __restrict__ Vh, __nv_bfloat16* __restrict__ Vl)
{
    int gw   = (blockIdx.x * blockDim.x + threadIdx.x) >> 5;
    int lane = threadIdx.x & 31;
    int m    = gw >> 5;
    int slot = gw & 31;
    int b = m >> 11;
    int t = m & (SEQ - 1);

    if (slot < 24) {
        float r0, r1, r2, r3;
        __nv_bfloat16 *dh, *dl;
        float extra;
        if (slot < 16) {
            int h = slot;
            const float* base = Qraw + (size_t)m * EMBD + h * HDIM;
            r0 = base[lane];      r1 = base[lane + 32];
            r2 = base[lane + 64]; r3 = base[lane + 96];
            size_t off = ((size_t)(b*NHEAD + h) * SEQ + t) * HDIM;
            dh = Qh + off; dl = Ql + off;
            extra = QK_SCALE;
        } else {
            int kvh = slot - 16;
            int mprev = (t > 0) ? (m - 1) : m;
            const float* bl = Kraw + (size_t)m     * KVDIM + kvh * HDIM;
            const float* bu = Kraw + (size_t)mprev * KVDIM + kvh * HDIM;
            r0 = bl[lane];      r1 = bl[lane + 32];
            r2 = bu[lane + 64]; r3 = bu[lane + 96];
            size_t off = ((size_t)(b*NKV + kvh) * SEQ + t) * HDIM;
            dh = Kh + off; dl = Kl + off;
            extra = 1.0f;
        }
        float c0 = cosp[t*HALF + lane], c1 = cosp[t*HALF + lane + 32];
        float s0 = sinp[t*HALF + lane], s1 = sinp[t*HALF + lane + 32];
        float o0 = r0*c0 + r2*s0;
        float o1 = r1*c1 + r3*s1;
        float o2 = r2*c0 - r0*s0;
        float o3 = r3*c1 - r1*s1;
        float ss = o0*o0 + o1*o1 + o2*o2 + o3*o3;
#pragma unroll
        for (int off = 16; off; off >>= 1)
            ss += __shfl_xor_sync(0xffffffffu, ss, off);
        float rn = rsqrtf(ss * (1.0f/128.0f) + 1.1920929e-7f) * extra;
        __nv_bfloat16 hh, ll;
        split1(o0*rn, hh, ll); dh[lane]      = hh; dl[lane]      = ll;
        split1(o1*rn, hh, ll); dh[lane + 32] = hh; dl[lane + 32] = ll;
        split1(o2*rn, hh, ll); dh[lane + 64] = hh; dl[lane + 64] = ll;
        split1(o3*rn, hh, ll); dh[lane + 96] = hh; dl[lane + 96] = ll;
    } else {
        int kvh = slot - 24;
        float g = G[m*8 + kvh];
        size_t src = (size_t)m * KVDIM + kvh * HDIM;
        size_t dst = ((size_t)(b*NKV + kvh) * SEQ + t) * HDIM;
        __nv_bfloat16 hh, ll;
#pragma unroll
        for (int d = lane; d < HDIM; d += 32) {
            float v = Vraw[src + d] + g * ve[src + d];
            split1(v, hh, ll);
            Vh[dst + d] = hh; Vl[dst + d] = ll;
        }
    }
}

// ---------------------------------------------------------------------------
// HMMA flash attention (bf16x3), sliding window 0 <= dist <= W.
// CTA: 128 q-rows x (head, batch); 8 warps x 16 q-rows; key tiles of 64.
// smem layout: sQh | sQl | sKh | sKl | sVh | sVl
// ---------------------------------------------------------------------------
#define AQSTR 136
#define Q_SM_ELEM (128*AQSTR)   // 17408
#define K_SM_ELEM (64*AQSTR)    // 8704
#define ATTN_SMEM_BYTES ((2*Q_SM_ELEM + 4*K_SM_ELEM) * 2)   // 139264

__global__ void __launch_bounds__(256, 1) attn_hmma_kernel(
    const __nv_bfloat16* __restrict__ Qh, const __nv_bfloat16* __restrict__ Ql,
    const __nv_bfloat16* __restrict__ Kh, const __nv_bfloat16* __restrict__ Kl,
    const __nv_bfloat16* __restrict__ Vh, const __nv_bfloat16* __restrict__ Vl,
    const float* __restrict__ AG,
    __nv_bfloat16* __restrict__ Yh, __nv_bfloat16* __restrict__ Yl,
    const int* __restrict__ wptr)
{
    extern __shared__ __nv_bfloat16 sb[];
    __nv_bfloat16* sQh = sb;
    __nv_bfloat16* sQl = sQh + Q_SM_ELEM;
    __nv_bfloat16* sKh = sQl + Q_SM_ELEM;
    __nv_bfloat16* sKl = sKh + K_SM_ELEM;
    __nv_bfloat16* sVh = sKl + K_SM_ELEM;
    __nv_bfloat16* sVl = sVh + K_SM_ELEM;

    const int tid = threadIdx.x;
    const int w = tid >> 5, lane = tid & 31;
    const int qb = blockIdx.x, h = blockIdx.y, b = blockIdx.z;
    const int kvh = h >> 1;
    const int q0 = qb * 128;

    int W = 1024;
    if (wptr) {
        int iv = wptr[0];
        if (iv > 0 && iv < (1 << 20)) W = iv;
        else {
            float fv = __int_as_float(iv);
            if (fv > 0.f && fv < 1.0e6f) W = (int)fv;
        }
    }

    // load Q tile (rows q0..q0+127, full D)
    {
        const __nv_bfloat16* gqh = Qh + ((size_t)(b*NHEAD + h) * SEQ + q0) * HDIM;
        const __nv_bfloat16* gql = Ql + ((size_t)(b*NHEAD + h) * SEQ + q0) * HDIM;
#pragma unroll
        for (int r = 0; r < 8; ++r) {
            int id  = tid + r*256;
            int row = id >> 4, ch = (id & 15) * 8;
            *(uint4*)(sQh + row*AQSTR + ch) = *(const uint4*)(gqh + (size_t)row*HDIM + ch);
            *(uint4*)(sQl + row*AQSTR + ch) = *(const uint4*)(gql + (size_t)row*HDIM + ch);
        }
    }

    float o[16][4];
#pragma unroll
    for (int i = 0; i < 16; ++i)
#pragma unroll
        for (int j = 0; j < 4; ++j) o[i][j] = 0.f;
    float mrow0 = -1.0e30f, mrow1 = -1.0e30f, lrow0 = 0.f, lrow1 = 0.f;

    int kstart = q0 - W; if (kstart < 0) kstart = 0;
    kstart &= ~63;

    const size_t kvbase = ((size_t)(b*NKV + kvh) * SEQ) * HDIM;
    const int qlo = q0 + w*16, qhi = qlo + 15;
    const int r_lo = lane >> 2;                  // row within warp tile
    const int cgrp = (lane & 3) * 2;             // col pair base

    for (int k0 = kstart; k0 < q0 + 128; k0 += 64) {
        __syncthreads();
        // load K/V tiles (64 keys)
#pragma unroll
        for (int r = 0; r < 4; ++r) {
            int id  = tid + r*256;
            int row = id >> 4, ch = (id & 15) * 8;
            size_t go = kvbase + (size_t)(k0 + row) * HDIM + ch;
            *(uint4*)(sKh + row*AQSTR + ch) = *(const uint4*)(Kh + go);
            *(uint4*)(sKl + row*AQSTR + ch) = *(const uint4*)(Kl + go);
            *(uint4*)(sVh + row*AQSTR + ch) = *(const uint4*)(Vh + go);
            *(uint4*)(sVl + row*AQSTR + ch) = *(const uint4*)(Vl + go);
        }
        __syncthreads();

        // warp-level tile skip (entire tile masked for all 16 rows)
        if (k0 > qhi || k0 + 63 < qlo - W) continue;

        // ---- S = Q K^T (16 x 64) ----
        float sacc[8][4];
#pragma unroll
        for (int nt = 0; nt < 8; ++nt)
#pragma unroll
            for (int j = 0; j < 4; ++j) sacc[nt][j] = 0.f;

#pragma unroll
        for (int ks = 0; ks < 8; ++ks) {
            uint32_t qh4[4], ql4[4];
            uint32_t qoff = smem_u32(sQh + (w*16 + (lane & 15))*AQSTR + ks*16 + (lane >> 4)*8);
            ldsm_x4(qh4, qoff);
            ldsm_x4(ql4, qoff + (uint32_t)(Q_SM_ELEM*2));
            uint32_t kh4[4][4], kl4[4][4];
#pragma unroll
            for (int g2 = 0; g2 < 4; ++g2) {
                uint32_t koff = smem_u32(sKh + (g2*16 + (lane & 15))*AQSTR + ks*16 + (lane >> 4)*8);
                ldsm_x4(kh4[g2], koff);
                ldsm_x4(kl4[g2], koff + (uint32_t)(K_SM_ELEM*2));
            }
#pragma unroll
            for (int g2 = 0; g2 < 4; ++g2)
#pragma unroll
                for (int sub = 0; sub < 2; ++sub) {
                    int nt = 2*g2 + sub;
                    uint32_t bh2[2] = {kh4[g2][sub], kh4[g2][sub + 2]};
                    uint32_t bl2[2] = {kl4[g2][sub], kl4[g2][sub + 2]};
                    mma16816(sacc[nt], qh4, bh2);
                    mma16816(sacc[nt], ql4, bh2);
                    mma16816(sacc[nt], qh4, bl2);
                }
        }

        // ---- mask + online softmax ----
        const int qi0 = qlo + r_lo, qi1 = qi0 + 8;
        float mx0 = -1.0e30f, mx1 = -1.0e30f;
#pragma unroll
        for (int nt = 0; nt < 8; ++nt) {
            int c0 = k0 + nt*8 + cgrp, c1 = c0 + 1;
            int d00 = qi0 - c0, d01 = qi0 - c1, d10 = qi1 - c0, d11 = qi1 - c1;
            sacc[nt][0] = (d00 >= 0 && d00 <= W) ? sacc[nt][0] : -1.0e30f;
            sacc[nt][1] = (d01 >= 0 && d01 <= W) ? sacc[nt][1] : -1.0e30f;
            sacc[nt][2] = (d10 >= 0 && d10 <= W) ? sacc[nt][2] : -1.0e30f;
            sacc[nt][3] = (d11 >= 0 && d11 <= W) ? sacc[nt][3] : -1.0e30f;
            mx0 = fmaxf(mx0, fmaxf(sacc[nt][0], sacc[nt][1]));
            mx1 = fmaxf(mx1, fmaxf(sacc[nt][2], sacc[nt][3]));
        }
        mx0 = fmaxf(mx0, __shfl_xor_sync(0xffffffffu, mx0, 1));
        mx0 = fmaxf(mx0, __shfl_xor_sync(0xffffffffu, mx0, 2));
        mx1 = fmaxf(mx1, __shfl_xor_sync(0xffffffffu, mx1, 1));
        mx1 = fmaxf(mx1, __shfl_xor_sync(0xffffffffu, mx1, 2));

        float mnew0 = fmaxf(mrow0, mx0), mnew1 = fmaxf(mrow1, mx1);
        float alpha0 = __expf(mrow0 - mnew0), alpha1 = __expf(mrow1 - mnew1);
        bool dead0 = (mnew0 < -1.0e29f), dead1 = (mnew1 < -1.0e29f);

        float ls0 = 0.f, ls1 = 0.f;
#pragma unroll
        for (int nt = 0; nt < 8; ++nt) {
            float p0 = dead0 ? 0.f : __expf(sacc[nt][0] - mnew0);
            float p1 = dead0 ? 0.f : __expf(sacc[nt][1] - mnew0);
            float p2 = dead1 ? 0.f : __expf(sacc[nt][2] - mnew1);
            float p3 = dead1 ? 0.f : __expf(sacc[nt][3] - mnew1);
            sacc[nt][0] = p0; sacc[nt][1] = p1; sacc[nt][2] = p2; sacc[nt][3] = p3;
            ls0 += p0 + p1; ls1 += p2 + p3;
        }
        ls0 += __shfl_xor_sync(0xffffffffu, ls0, 1);
        ls0 += __shfl_xor_sync(0xffffffffu, ls0, 2);
        ls1 += __shfl_xor_sync(0xffffffffu, ls1, 1);
        ls1 += __shfl_xor_sync(0xffffffffu, ls1, 2);

        lrow0 = lrow0 * alpha0 + ls0;  mrow0 = mnew0;
        lrow1 = lrow1 * alpha1 + ls1;  mrow1 = mnew1;

        // rescale O
#pragma unroll
        for (int ntd = 0; ntd < 16; ++ntd) {
            o[ntd][0] *= alpha0; o[ntd][1] *= alpha0;
            o[ntd][2] *= alpha1; o[ntd][3] *= alpha1;
        }

        // P -> A fragments (hi/lo)
        uint32_t pha[4][4], pla[4][4];
#pragma unroll
        for (int kc = 0; kc < 4; ++kc) {
            split2(sacc[2*kc][0],   sacc[2*kc][1],   pha[kc][0], pla[kc][0]);
            split2(sacc[2*kc][2],   sacc[2*kc][3],   pha[kc][1], pla[kc][1]);
            split2(sacc[2*kc+1][0], sacc[2*kc+1][1], pha[kc][2], pla[kc][2]);
            split2(sacc[2*kc+1][2], sacc[2*kc+1][3], pha[kc][3], pla[kc][3]);
        }

        // ---- O += P V ----
#pragma unroll
        for (int kc = 0; kc < 4; ++kc) {
#pragma unroll
            for (int dt = 0; dt < 8; ++dt) {
                uint32_t vh4[4], vl4[4];
                uint32_t voff = smem_u32(sVh + (kc*16 + (lane & 15))*AQSTR + dt*16 + (lane >> 4)*8);
                ldsm_x4_t(vh4, voff);
                ldsm_x4_t(vl4, voff + (uint32_t)(K_SM_ELEM*2));   // sVl immediately follows sVh
#pragma unroll
                for (int sub = 0; sub < 2; ++sub) {
                    int ntd = 2*dt + sub;
                    mma16816(o[ntd], pha[kc], &vh4[sub*2]);
                    mma16816(o[ntd], pla[kc], &vh4[sub*2]);
                    mma16816(o[ntd], pha[kc], &vl4[sub*2]);
                }
            }
        }
    }

    // ---- epilogue: gate/l, split to bf16 hi/lo Y ----
    {
        int m0r = b*SEQ + qlo + r_lo;
        float g0 = AG[m0r*NHEAD + h];
        float g1 = AG[(m0r + 8)*NHEAD + h];
        float inv0 = g0 / lrow0, inv1 = g1 / lrow1;
#pragma unroll
        for (int ntd = 0; ntd < 16; ++ntd) {
            int col = h*HDIM + ntd*8 + cgrp;
            uint32_t hi, lo;
            split2(o[ntd][0]*inv0, o[ntd][1]*inv0, hi, lo);
            *(uint32_t*)&Yh[(size_t)m0r*EMBD + col] = hi;
            *(uint32_t*)&Yl[(size_t)m0r*EMBD + col] = lo;
            split2(o[ntd][2]*inv1, o[ntd][3]*inv1, hi, lo);
            *(uint32_t*)&Yh[(size_t)(m0r + 8)*EMBD + col] = hi;
            *(uint32_t*)&Yl[(size_t)(m0r + 8)*EMBD + col] = lo;
        }
    }
}

// ---------------------------------------------------------------------------
// Launch
// ---------------------------------------------------------------------------
extern "C" void kernel_launch(void* const* d_in, const int* in_sizes, int n_in,
                              void* d_out, int out_size)
{
    const float* x     = (const float*)d_in[0];
    const float* ve    = (const float*)d_in[1];
    const float* cosp  = (const float*)d_in[2];
    const float* sinp  = (const float*)d_in[3];
    const float* wq    = (const float*)d_in[4];
    const float* wk    = (const float*)d_in[5];
    const float* wv    = (const float*)d_in[6];
    const float* wproj = (const float*)d_in[7];
    const float* wg    = (const float*)d_in[8];
    const float* wa    = (const float*)d_in[9];
    const float* ps    = (const float*)d_in[10];
    const int*   wsz   = (n_in > 11) ? (const int*)d_in[11] : nullptr;

    float *Qraw, *Kraw, *Vraw, *G, *AG;
    __nv_bfloat16 *Xh, *Xl, *Wqh, *Wql, *Wkh, *Wkl, *Wvh, *Wvl, *Wph, *Wpl;
    __nv_bfloat16 *Qbh, *Qbl, *Kbh, *Kbl, *Vbh, *Vbl, *Yh, *Yl;
    cudaGetSymbolAddress((void**)&Qraw, d_Qraw);
    cudaGetSymbolAddress((void**)&Kraw, d_Kraw);
    cudaGetSymbolAddress((void**)&Vraw, d_Vraw);
    cudaGetSymbolAddress((void**)&G,    d_G);
    cudaGetSymbolAddress((void**)&AG,   d_AG);
    cudaGetSymbolAddress((void**)&Xh,   d_Xh);   cudaGetSymbolAddress((void**)&Xl,  d_Xl);
    cudaGetSymbolAddress((void**)&Wqh,  d_Wqh);  cudaGetSymbolAddress((void**)&Wql, d_Wql);
    cudaGetSymbolAddress((void**)&Wkh,  d_Wkh);  cudaGetSymbolAddress((void**)&Wkl, d_Wkl);
    cudaGetSymbolAddress((void**)&Wvh,  d_Wvh);  cudaGetSymbolAddress((void**)&Wvl, d_Wvl);
    cudaGetSymbolAddress((void**)&Wph,  d_Wph);  cudaGetSymbolAddress((void**)&Wpl, d_Wpl);
    cudaGetSymbolAddress((void**)&Qbh,  d_Qbh);  cudaGetSymbolAddress((void**)&Qbl, d_Qbl);
    cudaGetSymbolAddress((void**)&Kbh,  d_Kbh);  cudaGetSymbolAddress((void**)&Kbl, d_Kbl);
    cudaGetSymbolAddress((void**)&Vbh,  d_Vbh);  cudaGetSymbolAddress((void**)&Vbl, d_Vbl);
    cudaGetSymbolAddress((void**)&Yh,   d_Yh);   cudaGetSymbolAddress((void**)&Yl,  d_Yl);

    // 0: pre-split x and weights into bf16 hi/lo
    {
        int n4;
        n4 = MROWS*EMBD/4;  split_kernel<<<(n4+255)/256, 256>>>(x,     Xh,  Xl,  n4);
        n4 = EMBD*EMBD/4;   split_kernel<<<(n4+255)/256, 256>>>(wq,    Wqh, Wql, n4);
        n4 = EMBD*KVDIM/4;  split_kernel<<<(n4+255)/256, 256>>>(wk,    Wkh, Wkl, n4);
        n4 = EMBD*KVDIM/4;  split_kernel<<<(n4+255)/256, 256>>>(wv,    Wvh, Wvl, n4);
        n4 = EMBD*EMBD/4;   split_kernel<<<(n4+255)/256, 256>>>(wproj, Wph, Wpl, n4);
    }

    cudaFuncSetAttribute(gemm_bf16x3_kernel, cudaFuncAttributeMaxDynamicSharedMemorySize, GEMM_SMEM_BYTES);
    cudaFuncSetAttribute(attn_hmma_kernel,   cudaFuncAttributeMaxDynamicSharedMemorySize, ATTN_SMEM_BYTES);

    // 1-3: projections
    gemm_bf16x3_kernel<<<dim3(EMBD/128,  MROWS/128), 256, GEMM_SMEM_BYTES>>>(Xh, Xl, Wqh, Wql, Qraw, MROWS, EMBD,  EMBD, nullptr);
    gemm_bf16x3_kernel<<<dim3(KVDIM/128, MROWS/128), 256, GEMM_SMEM_BYTES>>>(Xh, Xl, Wkh, Wkl, Kraw, MROWS, KVDIM, EMBD, nullptr);
    gemm_bf16x3_kernel<<<dim3(KVDIM/128, MROWS/128), 256, GEMM_SMEM_BYTES>>>(Xh, Xl, Wvh, Wvl, Vraw, MROWS, KVDIM, EMBD, nullptr);

    // 4: gates
    gates_kernel<<<(MROWS*24 + 255)/256, 256>>>(x, wg, wa, G, AG);

    // 5: k-shift + rope + rmsnorm + v-gate -> bf16 hi/lo tensors
    post_kernel<<<(MROWS*32)/8, 256>>>(Qraw, Kraw, Vraw, ve, cosp, sinp, G,
                                       Qbh, Qbl, Kbh, Kbl, Vbh, Vbl);

    // 6: attention (HMMA)
    attn_hmma_kernel<<<dim3(SEQ/128, NHEAD, BATCH), 256, ATTN_SMEM_BYTES>>>(
        Qbh, Qbl, Kbh, Kbl, Vbh, Vbl, AG, Yh, Yl, wsz);

    // 7: output projection with (1 + proj_scalar)
    gemm_bf16x3_kernel<<<dim3(EMBD/128, MROWS/128), 256, GEMM_SMEM_BYTES>>>(Yh, Yl, Wph, Wpl, (float*)d_out, MROWS, EMBD, EMBD, ps);
}